// round 13
// baseline (speedup 1.0000x reference)
#include <cuda_runtime.h>
#include <cuda_bf16.h>
#include <math.h>
#include <cstdint>

#define Bsz 512
#define Lq  196
#define Cc  384
#define NHh 12
#define HD  32
#define BH  (Bsz*NHh)      // 6144
#define MT  (Bsz*Lq)       // 100352
#define NQKV (3*Cc)        // 1152
#define Kdim 384
#define QSCALE 0.17677669529663687f  // 32^-0.5

// ---------------- scratch ----------------
__device__ uint32_t g_qh[(size_t)BH*Lq*16];
__device__ uint32_t g_ql[(size_t)BH*Lq*16];
__device__ uint32_t g_kh[(size_t)BH*Lq*16];
__device__ uint32_t g_kl[(size_t)BH*Lq*16];
__device__ float    g_v [(size_t)BH*Lq*HD];
__device__ float    g_attnout[(size_t)MT*Cc];
__device__ float    g_bias[NHh*Lq*Lq];

// ---------------- helpers ----------------
__device__ __forceinline__ void bf16_split2(float x0, float x1, uint32_t& hi, uint32_t& lo) {
    __nv_bfloat16 h0 = __float2bfloat16(x0), h1 = __float2bfloat16(x1);
    float l0 = x0 - __bfloat162float(h0);
    float l1 = x1 - __bfloat162float(h1);
    __nv_bfloat162 hp, lp;
    hp.x = h0; hp.y = h1;
    lp.x = __float2bfloat16(l0); lp.y = __float2bfloat16(l1);
    hi = *(uint32_t*)&hp;
    lo = *(uint32_t*)&lp;
}
__device__ __forceinline__ float2 unpack_bf2(uint32_t u) {
    __nv_bfloat162 b = *(__nv_bfloat162*)&u;
    return make_float2(__bfloat162float(b.x), __bfloat162float(b.y));
}
__device__ __forceinline__ void mma16(float* c, const uint32_t* a, const uint32_t* b) {
    asm volatile("mma.sync.aligned.m16n8k16.row.col.f32.bf16.bf16.f32 "
        "{%0,%1,%2,%3}, {%4,%5,%6,%7}, {%8,%9}, {%0,%1,%2,%3};"
        : "+f"(c[0]), "+f"(c[1]), "+f"(c[2]), "+f"(c[3])
        : "r"(a[0]), "r"(a[1]), "r"(a[2]), "r"(a[3]), "r"(b[0]), "r"(b[1]));
}
__device__ __forceinline__ int perm8(int p) {
    return (p >> 3) * 8 + (p & 3) * 2 + ((p >> 2) & 1);
}

// ---------------- bias expand ----------------
__global__ void bias_expand(const float* __restrict__ bt, const int* __restrict__ ridx) {
    int i = blockIdx.x * 256 + threadIdx.x;
    if (i < Lq*Lq) {
        int r = ridx[i];
        #pragma unroll
        for (int h = 0; h < NHh; h++)
            g_bias[h*(Lq*Lq) + i] = bt[r*NHh + h];
    }
}

// ---------------- GEMM mainloop: 3xBF16 mma.sync, 256 thr, warp tile 64x32 ----------------
// CTA tile 128x128x32. Warp grid 2(m) x 4(n). Same fragment-order smem as R8.
struct GemmSmem {
    uint32_t AsH[16][128];
    uint32_t AsL[16][128];
    uint32_t BsH[32][64];
    uint32_t BsL[32][64];
};

__device__ __forceinline__ void gemm_mainloop_bf16(const float* __restrict__ A,
                                                   const float* __restrict__ B,
                                                   int Nld, int m0, int n0,
                                                   float acc[4][4][4], GemmSmem* S)
{
    const int t    = threadIdx.x;
    const int lane = t & 31;
    const int wid  = t >> 5;            // 0..7
    const int wm   = wid >> 2;          // 0..1
    const int wn   = wid & 3;           // 0..3

    // A loader: row = t>>1 (0..127), float4 cols c = (t&1)*4 + j, j=0..3
    const int arow = t >> 1;
    const int ac0  = (t & 1) * 4;
    // B loader: n = t&127, 16 consecutive k starting at (t>>7)*16
    const int bn = t & 127;
    const int kq = t >> 7;              // 0..1

    float4 pa[4];
    float  pb[16];
    #pragma unroll
    for (int j = 0; j < 4; j++)
        pa[j] = *(const float4*)(A + (size_t)(m0 + arow)*Kdim + (ac0 + j)*4);
    #pragma unroll
    for (int e = 0; e < 16; e++)
        pb[e] = B[(size_t)(kq*16 + e)*Nld + n0 + bn];

    const int matom = arow >> 4;        // 0..7
    const int rowm  = arow & 15;
    const int natom = bn >> 3;          // 0..15
    const int ncol  = bn & 7;

    for (int ch = 0; ch < 12; ch++) {
        __syncthreads();
        // ---- store pre-split A fragments ----
        #pragma unroll
        for (int j = 0; j < 4; j++) {
            int kb  = (ac0 + j) * 4;        // 0,4,...,28
            int kc  = kb >> 4;
            int kkl = kb & 15;
            int lane0 = (rowm & 7)*4 + ((kkl & 7) >> 1);
            int reg   = ((rowm >> 3) & 1) | ((kkl >> 3) << 1);
            uint32_t h01, l01, h23, l23;
            bf16_split2(pa[j].x, pa[j].y, h01, l01);
            bf16_split2(pa[j].z, pa[j].w, h23, l23);
            int blk = matom*2 + kc;
            S->AsH[blk][lane0*4 + reg]     = h01;
            S->AsL[blk][lane0*4 + reg]     = l01;
            S->AsH[blk][(lane0+1)*4 + reg] = h23;
            S->AsL[blk][(lane0+1)*4 + reg] = l23;
        }
        // ---- store pre-split B fragments ----
        {
            int blk = natom*2 + kq;
            #pragma unroll
            for (int p = 0; p < 8; p++) {
                uint32_t h, l;
                bf16_split2(pb[2*p], pb[2*p+1], h, l);
                int ln = ncol*4 + (p & 3);
                int rg = p >> 2;
                S->BsH[blk][ln*2 + rg] = h;
                S->BsL[blk][ln*2 + rg] = l;
            }
        }
        __syncthreads();
        // ---- prefetch next k-tile ----
        if (ch < 11) {
            int k0n = (ch + 1)*32;
            #pragma unroll
            for (int j = 0; j < 4; j++)
                pa[j] = *(const float4*)(A + (size_t)(m0 + arow)*Kdim + k0n + (ac0 + j)*4);
            #pragma unroll
            for (int e = 0; e < 16; e++)
                pb[e] = B[(size_t)(k0n + kq*16 + e)*Nld + n0 + bn];
        }
        // ---- mma ----
        #pragma unroll
        for (int kc = 0; kc < 2; kc++) {
            uint4 AH[4], AL[4];
            uint2 BHf[4], BLf[4];
            #pragma unroll
            for (int im = 0; im < 4; im++) {
                int blk = (wm*4 + im)*2 + kc;
                AH[im] = *(const uint4*)&S->AsH[blk][lane*4];
                AL[im] = *(const uint4*)&S->AsL[blk][lane*4];
            }
            #pragma unroll
            for (int in_ = 0; in_ < 4; in_++) {
                int blk = (wn*4 + in_)*2 + kc;
                BHf[in_] = *(const uint2*)&S->BsH[blk][lane*2];
                BLf[in_] = *(const uint2*)&S->BsL[blk][lane*2];
            }
            #pragma unroll
            for (int im = 0; im < 4; im++)
                #pragma unroll
                for (int in_ = 0; in_ < 4; in_++) {
                    mma16(acc[im][in_], (const uint32_t*)&AH[im], (const uint32_t*)&BHf[in_]);
                    mma16(acc[im][in_], (const uint32_t*)&AH[im], (const uint32_t*)&BLf[in_]);
                    mma16(acc[im][in_], (const uint32_t*)&AL[im], (const uint32_t*)&BHf[in_]);
                }
        }
    }
}

// ---------------- kernel: QKV GEMM ----------------
__global__ __launch_bounds__(256) void qkv_mma(const float* __restrict__ x,
                                               const float* __restrict__ w,
                                               const float* __restrict__ qb) {
    __shared__ GemmSmem S;
    float acc[4][4][4];
    #pragma unroll
    for (int i = 0; i < 4; i++)
        #pragma unroll
        for (int j = 0; j < 4; j++)
            #pragma unroll
            for (int k = 0; k < 4; k++) acc[i][j][k] = 0.f;

    const int m0 = blockIdx.y * 128, n0 = blockIdx.x * 128;
    gemm_mainloop_bf16(x, w, NQKV, m0, n0, acc, &S);

    const int lane = threadIdx.x & 31, wid = threadIdx.x >> 5;
    const int wm = wid >> 2, wn = wid & 3;
    #pragma unroll
    for (int im = 0; im < 4; im++) {
        #pragma unroll
        for (int in_ = 0; in_ < 4; in_++) {
            int n = n0 + wn*32 + in_*8 + (lane & 3)*2;
            int seg = n / Cc, rem = n - seg*Cc;
            int h = rem >> 5, d = rem & 31;
            float sc = (seg == 0) ? QSCALE : 1.f;
            float b0 = qb[n], b1 = qb[n + 1];
            #pragma unroll
            for (int half = 0; half < 2; half++) {
                int m = m0 + wm*64 + im*16 + (lane >> 2) + half*8;
                int bb = m / Lq, l = m - bb*Lq;
                float o0 = (acc[im][in_][half*2 + 0] + b0) * sc;
                float o1 = (acc[im][in_][half*2 + 1] + b1) * sc;
                if (seg < 2) {
                    uint32_t hi, lo;
                    bf16_split2(o0, o1, hi, lo);
                    size_t idx = ((size_t)(bb*NHh + h)*Lq + l)*16 + (d >> 1);
                    if (seg == 0) { g_qh[idx] = hi; g_ql[idx] = lo; }
                    else          { g_kh[idx] = hi; g_kl[idx] = lo; }
                } else {
                    float2 o = make_float2(o0, o1);
                    *(float2*)(g_v + ((size_t)(bb*NHh + h)*Lq + l)*HD + d) = o;
                }
            }
        }
    }
}

// ---------------- kernel: proj GEMM ----------------
__global__ __launch_bounds__(256) void proj_mma(const float* __restrict__ w,
                                                const float* __restrict__ pb,
                                                float* __restrict__ out) {
    __shared__ GemmSmem S;
    float acc[4][4][4];
    #pragma unroll
    for (int i = 0; i < 4; i++)
        #pragma unroll
        for (int j = 0; j < 4; j++)
            #pragma unroll
            for (int k = 0; k < 4; k++) acc[i][j][k] = 0.f;

    const int m0 = blockIdx.y * 128, n0 = blockIdx.x * 128;
    gemm_mainloop_bf16(g_attnout, w, Cc, m0, n0, acc, &S);

    const int lane = threadIdx.x & 31, wid = threadIdx.x >> 5;
    const int wm = wid >> 2, wn = wid & 3;
    #pragma unroll
    for (int im = 0; im < 4; im++) {
        #pragma unroll
        for (int in_ = 0; in_ < 4; in_++) {
            int n = n0 + wn*32 + in_*8 + (lane & 3)*2;
            float b0 = pb[n], b1 = pb[n + 1];
            #pragma unroll
            for (int half = 0; half < 2; half++) {
                int m = m0 + wm*64 + im*16 + (lane >> 2) + half*8;
                float2 o;
                o.x = acc[im][in_][half*2 + 0] + b0;
                o.y = acc[im][in_][half*2 + 1] + b1;
                *(float2*)(out + (size_t)m*Cc + n) = o;
            }
        }
    }
}

// ---------------- tensor-core attention, one block per (b, h) ----------------
#define PSTR 104
#define QSTR 16
#define KSTR 24
#define VSTR 120
#define ATTN_SMEM_BYTES 228880

__global__ __launch_bounds__(512) void attn_tc() {
    extern __shared__ uint32_t su[];
    uint32_t* SH = su;
    uint32_t* SL = su + 20384;
    uint32_t* QH = su + 40768;
    uint32_t* QL = su + 44096;
    uint32_t* KH = su + 47424;
    uint32_t* KL = su + 52224;
    float*  rowinv = (float*)(su + 57024);
    uint32_t* VH = su + 40768;
    uint32_t* VL = su + 44608;

    const int bh = blockIdx.x;
    const int h  = bh % NHh;
    const int tid = threadIdx.x, lane = tid & 31, wid = tid >> 5;
    const int r  = lane >> 2, cq = lane & 3;

    // ---- load packed Q/K pairs into permuted smem ----
    {
        const uint32_t* qh = g_qh + (size_t)bh*Lq*16;
        const uint32_t* ql = g_ql + (size_t)bh*Lq*16;
        const uint32_t* kh = g_kh + (size_t)bh*Lq*16;
        const uint32_t* kl = g_kl + (size_t)bh*Lq*16;
        for (int e = tid; e < Lq*16; e += 512) {
            int row = e >> 4, p = e & 15;
            int c = perm8(p);
            QH[row*QSTR + c] = qh[e];
            QL[row*QSTR + c] = ql[e];
            KH[row*KSTR + c] = kh[e];
            KL[row*KSTR + c] = kl[e];
        }
    }
    __syncthreads();

    // ---- QK^T: warps 0..12, one 16-row m-band each ----
    if (wid < 13) {
        const int m0 = wid * 16;
        uint32_t AH[2][4], AL[2][4];
        #pragma unroll
        for (int kc = 0; kc < 2; kc++) {
            uint2 t0 = *(uint2*)&QH[(m0 + r)*QSTR + kc*8 + cq*2];
            uint2 t1 = *(uint2*)&QH[(m0 + r + 8)*QSTR + kc*8 + cq*2];
            AH[kc][0] = t0.x; AH[kc][2] = t0.y; AH[kc][1] = t1.x; AH[kc][3] = t1.y;
            uint2 s0 = *(uint2*)&QL[(m0 + r)*QSTR + kc*8 + cq*2];
            uint2 s1 = *(uint2*)&QL[(m0 + r + 8)*QSTR + kc*8 + cq*2];
            AL[kc][0] = s0.x; AL[kc][2] = s0.y; AL[kc][1] = s1.x; AL[kc][3] = s1.y;
        }
        for (int na = 0; na < 25; na++) {
            float acc[4] = {0.f, 0.f, 0.f, 0.f};
            #pragma unroll
            for (int kc = 0; kc < 2; kc++) {
                uint2 bh2 = *(uint2*)&KH[(na*8 + r)*KSTR + kc*8 + cq*2];
                uint2 bl2 = *(uint2*)&KL[(na*8 + r)*KSTR + kc*8 + cq*2];
                uint32_t BH2[2] = {bh2.x, bh2.y};
                uint32_t BL2[2] = {bl2.x, bl2.y};
                mma16(acc, AH[kc], BH2);
                mma16(acc, AH[kc], BL2);
                mma16(acc, AL[kc], BH2);
            }
            int col = perm8(na*4 + cq);
            int row0 = m0 + r, row1 = row0 + 8;
            uint32_t hi, lo;
            if (row0 < Lq) {
                bf16_split2(acc[0], acc[1], hi, lo);
                SH[row0*PSTR + col] = hi; SL[row0*PSTR + col] = lo;
            }
            if (row1 < Lq) {
                bf16_split2(acc[2], acc[3], hi, lo);
                SH[row1*PSTR + col] = hi; SL[row1*PSTR + col] = lo;
            }
        }
    }
    __syncthreads();

    // ---- V transpose/split + two-pass softmax (R8 proven) ----
    {
        const float* vg = g_v + (size_t)bh*Lq*HD;
        for (int e = tid; e < 32*104; e += 512) {
            int n = e & 31, p = e >> 5;
            uint32_t hi = 0, lo = 0;
            if (p < 98) {
                float v0 = vg[(size_t)(2*p)*HD + n];
                float v1 = vg[(size_t)(2*p + 1)*HD + n];
                bf16_split2(v0, v1, hi, lo);
            }
            int c = perm8(p);
            VH[n*VSTR + c] = hi;
            VL[n*VSTR + c] = lo;
        }
        const float* brow_base = g_bias + h*(Lq*Lq);
        for (int row = wid; row < Lq; row += 16) {
            const float* brow = brow_base + row*Lq;
            float s[8];
            float mx = -1e30f;
            int cnt = 0;
            for (int p = lane; p < 98; p += 32) {
                float2 sh = unpack_bf2(SH[row*PSTR + perm8(p)]);
                float2 sl = unpack_bf2(SL[row*PSTR + perm8(p)]);
                float2 bb = *(const float2*)&brow[2*p];
                float s0 = sh.x + sl.x + bb.x;
                float s1 = sh.y + sl.y + bb.y;
                s[cnt*2]     = s0;
                s[cnt*2 + 1] = s1;
                cnt++;
                mx = fmaxf(mx, fmaxf(s0, s1));
            }
            #pragma unroll
            for (int o = 16; o > 0; o >>= 1) mx = fmaxf(mx, __shfl_xor_sync(0xffffffffu, mx, o));
            float sum = 0.f;
            int i2 = 0;
            for (int p = lane; p < 98; p += 32) {
                float p0 = __expf(s[i2*2]     - mx);
                float p1 = __expf(s[i2*2 + 1] - mx);
                i2++;
                sum += p0 + p1;
                uint32_t hi, lo;
                bf16_split2(p0, p1, hi, lo);
                SH[row*PSTR + perm8(p)] = hi;
                SL[row*PSTR + perm8(p)] = lo;
            }
            #pragma unroll
            for (int o = 16; o > 0; o >>= 1) sum += __shfl_xor_sync(0xffffffffu, sum, o);
            if (lane < 6) {
                const int zc[6] = {97, 99, 100, 101, 102, 103};
                SH[row*PSTR + zc[lane]] = 0;
                SL[row*PSTR + zc[lane]] = 0;
            }
            if (lane == 0) rowinv[row] = 1.f / sum;
        }
    }
    __syncthreads();

    // ---- P·V: warps 0..12, one 16-row m-band each ----
    if (wid < 13) {
        const int m0 = wid * 16;
        float acc[4][4];
        #pragma unroll
        for (int i = 0; i < 4; i++)
            #pragma unroll
            for (int j = 0; j < 4; j++) acc[i][j] = 0.f;

        for (int kc = 0; kc < 13; kc++) {
            uint32_t AH[4], AL[4];
            uint2 t0 = *(uint2*)&SH[(m0 + r)*PSTR + kc*8 + cq*2];
            uint2 t1 = *(uint2*)&SH[(m0 + r + 8)*PSTR + kc*8 + cq*2];
            AH[0] = t0.x; AH[2] = t0.y; AH[1] = t1.x; AH[3] = t1.y;
            uint2 s0 = *(uint2*)&SL[(m0 + r)*PSTR + kc*8 + cq*2];
            uint2 s1 = *(uint2*)&SL[(m0 + r + 8)*PSTR + kc*8 + cq*2];
            AL[0] = s0.x; AL[2] = s0.y; AL[1] = s1.x; AL[3] = s1.y;
            #pragma unroll
            for (int na = 0; na < 4; na++) {
                uint2 bh2 = *(uint2*)&VH[(na*8 + r)*VSTR + kc*8 + cq*2];
                uint2 bl2 = *(uint2*)&VL[(na*8 + r)*VSTR + kc*8 + cq*2];
                uint32_t BH2[2] = {bh2.x, bh2.y};
                uint32_t BL2[2] = {bl2.x, bl2.y};
                mma16(acc[na], AH, BH2);
                mma16(acc[na], AH, BL2);
                mma16(acc[na], AL, BH2);
            }
        }
        const int b = bh / NHh;
        float* og = g_attnout + (size_t)b*Lq*Cc + h*HD;
        int row0 = m0 + r, row1 = row0 + 8;
        #pragma unroll
        for (int na = 0; na < 4; na++) {
            int n = na*8 + cq*2;
            if (row0 < Lq) {
                float inv = rowinv[row0];
                float2 o = make_float2(acc[na][0]*inv, acc[na][1]*inv);
                *(float2*)(og + (size_t)row0*Cc + n) = o;
            }
            if (row1 < Lq) {
                float inv = rowinv[row1];
                float2 o = make_float2(acc[na][2]*inv, acc[na][3]*inv);
                *(float2*)(og + (size_t)row1*Cc + n) = o;
            }
        }
    }
}

// ---------------- launch ----------------
extern "C" void kernel_launch(void* const* d_in, const int* in_sizes, int n_in,
                              void* d_out, int out_size) {
    const float* x          = (const float*)d_in[0];
    const float* qkv_w      = (const float*)d_in[1];
    const float* qkv_b      = (const float*)d_in[2];
    const float* proj_w     = (const float*)d_in[3];
    const float* proj_b     = (const float*)d_in[4];
    const float* bias_table = (const float*)d_in[5];
    const int*   rel_index  = (const int*)d_in[6];
    float* out = (float*)d_out;

    cudaFuncSetAttribute(attn_tc, cudaFuncAttributeMaxDynamicSharedMemorySize, ATTN_SMEM_BYTES);

    bias_expand<<<(Lq*Lq + 255)/256, 256>>>(bias_table, rel_index);
    qkv_mma<<<dim3(NQKV/128, MT/128), 256>>>(x, qkv_w, qkv_b);
    attn_tc<<<BH, 512, ATTN_SMEM_BYTES>>>();
    proj_mma<<<dim3(Cc/128, MT/128), 256>>>(proj_w, proj_b, out);
}

// round 16
// speedup vs baseline: 1.4306x; 1.4306x over previous
#include <cuda_runtime.h>
#include <cuda_bf16.h>
#include <math.h>
#include <cstdint>

#define Bsz 512
#define Lq  196
#define Cc  384
#define NHh 12
#define HD  32
#define BH  (Bsz*NHh)      // 6144
#define MT  (Bsz*Lq)       // 100352
#define NQKV (3*Cc)        // 1152
#define Kdim 384
#define QSCALE 0.17677669529663687f  // 32^-0.5

// ---------------- scratch ----------------
__device__ uint32_t g_qh[(size_t)BH*Lq*16];
__device__ uint32_t g_ql[(size_t)BH*Lq*16];
__device__ uint32_t g_kh[(size_t)BH*Lq*16];
__device__ uint32_t g_kl[(size_t)BH*Lq*16];
__device__ float    g_v [(size_t)BH*Lq*HD];
__device__ float    g_attnout[(size_t)MT*Cc];
__device__ float    g_bias[NHh*Lq*Lq];

// ---------------- helpers ----------------
__device__ __forceinline__ void bf16_split2(float x0, float x1, uint32_t& hi, uint32_t& lo) {
    __nv_bfloat16 h0 = __float2bfloat16(x0), h1 = __float2bfloat16(x1);
    float l0 = x0 - __bfloat162float(h0);
    float l1 = x1 - __bfloat162float(h1);
    __nv_bfloat162 hp, lp;
    hp.x = h0; hp.y = h1;
    lp.x = __float2bfloat16(l0); lp.y = __float2bfloat16(l1);
    hi = *(uint32_t*)&hp;
    lo = *(uint32_t*)&lp;
}
__device__ __forceinline__ void mma16(float* c, const uint32_t* a, const uint32_t* b) {
    asm volatile("mma.sync.aligned.m16n8k16.row.col.f32.bf16.bf16.f32 "
        "{%0,%1,%2,%3}, {%4,%5,%6,%7}, {%8,%9}, {%0,%1,%2,%3};"
        : "+f"(c[0]), "+f"(c[1]), "+f"(c[2]), "+f"(c[3])
        : "r"(a[0]), "r"(a[1]), "r"(a[2]), "r"(a[3]), "r"(b[0]), "r"(b[1]));
}
__device__ __forceinline__ int perm8(int p) {
    return (p >> 3) * 8 + (p & 3) * 2 + ((p >> 2) & 1);
}

// ---------------- bias expand ----------------
__global__ void bias_expand(const float* __restrict__ bt, const int* __restrict__ ridx) {
    int i = blockIdx.x * 256 + threadIdx.x;
    if (i < Lq*Lq) {
        int r = ridx[i];
        #pragma unroll
        for (int h = 0; h < NHh; h++)
            g_bias[h*(Lq*Lq) + i] = bt[r*NHh + h];
    }
}

// ---------------- GEMM mainloop: 3xBF16 mma.sync, pre-split smem (R8 proven) ----------------
struct GemmSmem {
    uint32_t AsH[16][128];
    uint32_t AsL[16][128];
    uint32_t BsH[32][64];
    uint32_t BsL[32][64];
};

__device__ __forceinline__ void gemm_mainloop_bf16(const float* __restrict__ A,
                                                   const float* __restrict__ B,
                                                   int Nld, int m0, int n0,
                                                   float acc[2][4][4], GemmSmem* S)
{
    const int t    = threadIdx.x;
    const int lane = t & 31;
    const int wid  = t >> 5;
    const int wm   = wid >> 2, wn = wid & 3;

    const int arow = t >> 2;
    const int ac0  = t & 3;
    const int bn = t & 127;
    const int kq = t >> 7;

    float4 pa[2];
    float  pb[8];
    #pragma unroll
    for (int j = 0; j < 2; j++)
        pa[j] = *(const float4*)(A + (size_t)(m0 + arow)*Kdim + (ac0 + 4*j)*4);
    #pragma unroll
    for (int e = 0; e < 8; e++)
        pb[e] = B[(size_t)(kq*8 + e)*Nld + n0 + bn];

    const int matom = arow >> 4;
    const int rowm  = arow & 15;
    const int natom = bn >> 3;
    const int ncol  = bn & 7;

    for (int ch = 0; ch < 12; ch++) {
        __syncthreads();
        #pragma unroll
        for (int j = 0; j < 2; j++) {
            int kb  = (ac0 + 4*j) * 4;
            int kc  = kb >> 4;
            int kkl = kb & 15;
            int lane0 = (rowm & 7)*4 + ((kkl & 7) >> 1);
            int reg   = ((rowm >> 3) & 1) | ((kkl >> 3) << 1);
            uint32_t h01, l01, h23, l23;
            bf16_split2(pa[j].x, pa[j].y, h01, l01);
            bf16_split2(pa[j].z, pa[j].w, h23, l23);
            int blk = matom*2 + kc;
            S->AsH[blk][lane0*4 + reg]     = h01;
            S->AsL[blk][lane0*4 + reg]     = l01;
            S->AsH[blk][(lane0+1)*4 + reg] = h23;
            S->AsL[blk][(lane0+1)*4 + reg] = l23;
        }
        {
            int kc  = kq >> 1;
            int reg = kq & 1;
            int blk = natom*2 + kc;
            #pragma unroll
            for (int p = 0; p < 4; p++) {
                uint32_t h, l;
                bf16_split2(pb[2*p], pb[2*p+1], h, l);
                int ln = ncol*4 + p;
                S->BsH[blk][ln*2 + reg] = h;
                S->BsL[blk][ln*2 + reg] = l;
            }
        }
        __syncthreads();
        if (ch < 11) {
            int k0n = (ch + 1)*32;
            #pragma unroll
            for (int j = 0; j < 2; j++)
                pa[j] = *(const float4*)(A + (size_t)(m0 + arow)*Kdim + k0n + (ac0 + 4*j)*4);
            #pragma unroll
            for (int e = 0; e < 8; e++)
                pb[e] = B[(size_t)(k0n + kq*8 + e)*Nld + n0 + bn];
        }
        #pragma unroll
        for (int kc = 0; kc < 2; kc++) {
            uint4 AH[2], AL[2];
            uint2 BHf[4], BLf[4];
            #pragma unroll
            for (int im = 0; im < 2; im++) {
                int blk = (wm*2 + im)*2 + kc;
                AH[im] = *(const uint4*)&S->AsH[blk][lane*4];
                AL[im] = *(const uint4*)&S->AsL[blk][lane*4];
            }
            #pragma unroll
            for (int in_ = 0; in_ < 4; in_++) {
                int blk = (wn*4 + in_)*2 + kc;
                BHf[in_] = *(const uint2*)&S->BsH[blk][lane*2];
                BLf[in_] = *(const uint2*)&S->BsL[blk][lane*2];
            }
            #pragma unroll
            for (int im = 0; im < 2; im++)
                #pragma unroll
                for (int in_ = 0; in_ < 4; in_++) {
                    mma16(acc[im][in_], (const uint32_t*)&AH[im], (const uint32_t*)&BHf[in_]);
                    mma16(acc[im][in_], (const uint32_t*)&AH[im], (const uint32_t*)&BLf[in_]);
                    mma16(acc[im][in_], (const uint32_t*)&AL[im], (const uint32_t*)&BHf[in_]);
                }
        }
    }
}

// ---------------- kernel: QKV GEMM ----------------
__global__ __launch_bounds__(512) void qkv_mma(const float* __restrict__ x,
                                               const float* __restrict__ w,
                                               const float* __restrict__ qb) {
    __shared__ GemmSmem S;
    float acc[2][4][4];
    #pragma unroll
    for (int i = 0; i < 2; i++)
        #pragma unroll
        for (int j = 0; j < 4; j++)
            #pragma unroll
            for (int k = 0; k < 4; k++) acc[i][j][k] = 0.f;

    const int m0 = blockIdx.y * 128, n0 = blockIdx.x * 128;
    gemm_mainloop_bf16(x, w, NQKV, m0, n0, acc, &S);

    const int lane = threadIdx.x & 31, wid = threadIdx.x >> 5;
    const int wm = wid >> 2, wn = wid & 3;
    #pragma unroll
    for (int im = 0; im < 2; im++) {
        #pragma unroll
        for (int in_ = 0; in_ < 4; in_++) {
            int n = n0 + wn*32 + in_*8 + (lane & 3)*2;
            int seg = n / Cc, rem = n - seg*Cc;
            int h = rem >> 5, d = rem & 31;
            float sc = (seg == 0) ? QSCALE : 1.f;
            float b0 = qb[n], b1 = qb[n + 1];
            #pragma unroll
            for (int half = 0; half < 2; half++) {
                int m = m0 + wm*32 + im*16 + (lane >> 2) + half*8;
                int bb = m / Lq, l = m - bb*Lq;
                float o0 = (acc[im][in_][half*2 + 0] + b0) * sc;
                float o1 = (acc[im][in_][half*2 + 1] + b1) * sc;
                if (seg < 2) {
                    uint32_t hi, lo;
                    bf16_split2(o0, o1, hi, lo);
                    size_t idx = ((size_t)(bb*NHh + h)*Lq + l)*16 + (d >> 1);
                    if (seg == 0) { g_qh[idx] = hi; g_ql[idx] = lo; }
                    else          { g_kh[idx] = hi; g_kl[idx] = lo; }
                } else {
                    float2 o = make_float2(o0, o1);
                    *(float2*)(g_v + ((size_t)(bb*NHh + h)*Lq + l)*HD + d) = o;
                }
            }
        }
    }
}

// ---------------- kernel: proj GEMM ----------------
__global__ __launch_bounds__(512) void proj_mma(const float* __restrict__ w,
                                                const float* __restrict__ pb,
                                                float* __restrict__ out) {
    __shared__ GemmSmem S;
    float acc[2][4][4];
    #pragma unroll
    for (int i = 0; i < 2; i++)
        #pragma unroll
        for (int j = 0; j < 4; j++)
            #pragma unroll
            for (int k = 0; k < 4; k++) acc[i][j][k] = 0.f;

    const int m0 = blockIdx.y * 128, n0 = blockIdx.x * 128;
    gemm_mainloop_bf16(g_attnout, w, Cc, m0, n0, acc, &S);

    const int lane = threadIdx.x & 31, wid = threadIdx.x >> 5;
    const int wm = wid >> 2, wn = wid & 3;
    #pragma unroll
    for (int im = 0; im < 2; im++) {
        #pragma unroll
        for (int in_ = 0; in_ < 4; in_++) {
            int n = n0 + wn*32 + in_*8 + (lane & 3)*2;
            float b0 = pb[n], b1 = pb[n + 1];
            #pragma unroll
            for (int half = 0; half < 2; half++) {
                int m = m0 + wm*32 + im*16 + (lane >> 2) + half*8;
                float2 o;
                o.x = acc[im][in_][half*2 + 0] + b0;
                o.y = acc[im][in_][half*2 + 1] + b1;
                *(float2*)(out + (size_t)m*Cc + n) = o;
            }
        }
    }
}

// ---------------- flash attention: one block per (b,h), 13 warps, no S array ----------------
// smem (u32): KH [200][24] @0, KL @4800, VH [32][120] @9600, VL @13440; total 17280 u32 = 69120 B
#define KSTR 24
#define VSTR 120
#define ATTN_DSMEM 69120

__global__ __launch_bounds__(416, 2) void attn_flash() {
    extern __shared__ uint32_t su[];
    uint32_t* KH = su;
    uint32_t* KL = su + 4800;
    uint32_t* VH = su + 9600;
    uint32_t* VL = su + 13440;

    const int bh = blockIdx.x;
    const int h  = bh % NHh;
    const int b  = bh / NHh;
    const int tid = threadIdx.x, lane = tid & 31, wid = tid >> 5;
    const int r = lane >> 2, cq = lane & 3;

    // ---- cooperative load: K (permuted pairs) + V (transpose/split) ----
    {
        const uint32_t* kh = g_kh + (size_t)bh*Lq*16;
        const uint32_t* kl = g_kl + (size_t)bh*Lq*16;
        for (int e = tid; e < Lq*16; e += 416) {
            int row = e >> 4, p = e & 15;
            int c = perm8(p);
            KH[row*KSTR + c] = kh[e];
            KL[row*KSTR + c] = kl[e];
        }
        for (int e = tid; e < 64; e += 416) {        // zero pad rows 196..199
            int row = 196 + (e >> 4), c = e & 15;
            KH[row*KSTR + c] = 0;
            KL[row*KSTR + c] = 0;
        }
        const float* vg = g_v + (size_t)bh*Lq*HD;
        for (int e = tid; e < 32*104; e += 416) {
            int n = e & 31, p = e >> 5;
            uint32_t hi = 0, lo = 0;
            if (p < 98) {
                float v0 = vg[(size_t)(2*p)*HD + n];
                float v1 = vg[(size_t)(2*p + 1)*HD + n];
                bf16_split2(v0, v1, hi, lo);
            }
            int c = perm8(p);
            VH[n*VSTR + c] = hi;
            VL[n*VSTR + c] = lo;
        }
    }
    __syncthreads();

    // ---- per-warp: q-band of 16 rows, Q fragments from global ----
    const int row0 = wid*16 + r, row1 = row0 + 8;
    const int r0c = (row0 < 196) ? row0 : 195;
    const int r1c = (row1 < 196) ? row1 : 195;

    uint32_t QAH[2][4], QAL[2][4];
    {
        const uint32_t* qh = g_qh + (size_t)bh*Lq*16;
        const uint32_t* ql = g_ql + (size_t)bh*Lq*16;
        #pragma unroll
        for (int kc = 0; kc < 2; kc++) {
            QAH[kc][0] = qh[r0c*16 + kc*8 + cq];
            QAH[kc][1] = qh[r1c*16 + kc*8 + cq];
            QAH[kc][2] = qh[r0c*16 + kc*8 + cq + 4];
            QAH[kc][3] = qh[r1c*16 + kc*8 + cq + 4];
            QAL[kc][0] = ql[r0c*16 + kc*8 + cq];
            QAL[kc][1] = ql[r1c*16 + kc*8 + cq];
            QAL[kc][2] = ql[r0c*16 + kc*8 + cq + 4];
            QAL[kc][3] = ql[r1c*16 + kc*8 + cq + 4];
        }
    }

    float Oacc[4][4];
    #pragma unroll
    for (int i = 0; i < 4; i++)
        #pragma unroll
        for (int j = 0; j < 4; j++) Oacc[i][j] = 0.f;
    float sum0 = 0.f, sum1 = 0.f;

    const float* brow0 = g_bias + h*(Lq*Lq) + r0c*Lq;
    const float* brow1 = g_bias + h*(Lq*Lq) + r1c*Lq;

    for (int j = 0; j < 13; j++) {
        uint32_t PH[4], PL[4];
        // ---- atom 2j (A-frag regs 0,1) ----
        {
            const int na = 2*j;
            float acc[4] = {0.f, 0.f, 0.f, 0.f};
            #pragma unroll
            for (int kc = 0; kc < 2; kc++) {
                uint32_t bh2[2], bl2[2];
                *(uint2*)bh2 = *(const uint2*)&KH[(na*8 + r)*KSTR + kc*8 + cq*2];
                *(uint2*)bl2 = *(const uint2*)&KL[(na*8 + r)*KSTR + kc*8 + cq*2];
                mma16(acc, QAH[kc], bh2);
                mma16(acc, QAH[kc], bl2);
                mma16(acc, QAL[kc], bh2);
            }
            const int c0 = na*8 + cq*2;
            float p0, p1, p2, p3;
            if (c0 < 196) {
                float2 b0 = *(const float2*)&brow0[c0];
                float2 b1 = *(const float2*)&brow1[c0];
                p0 = __expf(acc[0] + b0.x);
                p1 = __expf(acc[1] + b0.y);
                p2 = __expf(acc[2] + b1.x);
                p3 = __expf(acc[3] + b1.y);
            } else { p0 = p1 = p2 = p3 = 0.f; }
            sum0 += p0 + p1;
            sum1 += p2 + p3;
            bf16_split2(p0, p1, PH[0], PL[0]);
            bf16_split2(p2, p3, PH[1], PL[1]);
        }
        // ---- atom 2j+1 (A-frag regs 2,3) ----
        if (j < 12) {
            const int na = 2*j + 1;
            float acc[4] = {0.f, 0.f, 0.f, 0.f};
            #pragma unroll
            for (int kc = 0; kc < 2; kc++) {
                uint32_t bh2[2], bl2[2];
                *(uint2*)bh2 = *(const uint2*)&KH[(na*8 + r)*KSTR + kc*8 + cq*2];
                *(uint2*)bl2 = *(const uint2*)&KL[(na*8 + r)*KSTR + kc*8 + cq*2];
                mma16(acc, QAH[kc], bh2);
                mma16(acc, QAH[kc], bl2);
                mma16(acc, QAL[kc], bh2);
            }
            const int c0 = na*8 + cq*2;
            float p0, p1, p2, p3;
            if (c0 < 196) {
                float2 b0 = *(const float2*)&brow0[c0];
                float2 b1 = *(const float2*)&brow1[c0];
                p0 = __expf(acc[0] + b0.x);
                p1 = __expf(acc[1] + b0.y);
                p2 = __expf(acc[2] + b1.x);
                p3 = __expf(acc[3] + b1.y);
            } else { p0 = p1 = p2 = p3 = 0.f; }
            sum0 += p0 + p1;
            sum1 += p2 + p3;
            bf16_split2(p0, p1, PH[2], PL[2]);
            bf16_split2(p2, p3, PH[3], PL[3]);
        } else {
            PH[2] = PH[3] = PL[2] = PL[3] = 0;
        }
        // ---- PV accumulate (k-step j) ----
        #pragma unroll
        for (int nd = 0; nd < 4; nd++) {
            uint32_t vh2[2], vl2[2];
            *(uint2*)vh2 = *(const uint2*)&VH[(nd*8 + r)*VSTR + j*8 + cq*2];
            *(uint2*)vl2 = *(const uint2*)&VL[(nd*8 + r)*VSTR + j*8 + cq*2];
            mma16(Oacc[nd], PH, vh2);
            mma16(Oacc[nd], PH, vl2);
            mma16(Oacc[nd], PL, vh2);
        }
    }

    // ---- normalize + write ----
    sum0 += __shfl_xor_sync(0xffffffffu, sum0, 1);
    sum0 += __shfl_xor_sync(0xffffffffu, sum0, 2);
    sum1 += __shfl_xor_sync(0xffffffffu, sum1, 1);
    sum1 += __shfl_xor_sync(0xffffffffu, sum1, 2);
    float inv0 = 1.f / sum0, inv1 = 1.f / sum1;

    float* og = g_attnout + (size_t)b*Lq*Cc + h*HD;
    #pragma unroll
    for (int nd = 0; nd < 4; nd++) {
        int n = nd*8 + cq*2;
        if (row0 < Lq) {
            float2 o = make_float2(Oacc[nd][0]*inv0, Oacc[nd][1]*inv0);
            *(float2*)(og + (size_t)row0*Cc + n) = o;
        }
        if (row1 < Lq) {
            float2 o = make_float2(Oacc[nd][2]*inv1, Oacc[nd][3]*inv1);
            *(float2*)(og + (size_t)row1*Cc + n) = o;
        }
    }
}

// ---------------- launch ----------------
extern "C" void kernel_launch(void* const* d_in, const int* in_sizes, int n_in,
                              void* d_out, int out_size) {
    const float* x          = (const float*)d_in[0];
    const float* qkv_w      = (const float*)d_in[1];
    const float* qkv_b      = (const float*)d_in[2];
    const float* proj_w     = (const float*)d_in[3];
    const float* proj_b     = (const float*)d_in[4];
    const float* bias_table = (const float*)d_in[5];
    const int*   rel_index  = (const int*)d_in[6];
    float* out = (float*)d_out;

    cudaFuncSetAttribute(attn_flash, cudaFuncAttributeMaxDynamicSharedMemorySize, ATTN_DSMEM);

    bias_expand<<<(Lq*Lq + 255)/256, 256>>>(bias_table, rel_index);
    qkv_mma<<<dim3(NQKV/128, MT/128), 512>>>(x, qkv_w, qkv_b);
    attn_flash<<<BH, 416, ATTN_DSMEM>>>();
    proj_mma<<<dim3(Cc/128, MT/128), 512>>>(proj_w, proj_b, out);
}